// round 17
// baseline (speedup 1.0000x reference)
#include <cuda_runtime.h>
#include <cuda_bf16.h>
#include <cstdint>
#include <cstddef>

// ---------------- problem constants ----------------
#define NUM_K 512
#define DIM   64
#define T_LEN 8192
#define B_LEN 32

#define MT    256
#define NTH   256
#define NCTA  1024                  // (B*T)/MT
#define CAND_W 6.0e-3f              // filter capture window (R7-proven margin)

// Output layout: [quantized B*D*T][loss 1][indices as float B*T]
#define LOSS_OFF ((size_t)B_LEN * DIM * T_LEN)
#define IDX_OFF  (LOSS_OFF + 1)

// ---------------- smem layout (bytes) ----------------
#define SM_X     0                  // fp32 [64][256]                 65536
#define SM_EP    65536              // ull  [128 pairs][65]           66560
#define SM_B     132096             // bf16 kword [256][36w]          36864
#define SM_SEE   168960             // fp32 [512]                      2048
#define SM_BM    171008             // u16  [256][33]                 16896
#define SM_REDV  187904             // fp32 [4][256]                   4096
#define SM_REDI  192000             // int  [4][256]                   4096
#define SM_SIDX  196096             // int  [256]                      1024
#define SM_REDW  197120             // fp32 [8] (+pad)                   64
#define SMEM_BYTES 197184
#define SM_CSTG  SM_B               // alias after refine: fp32[128][65]=33280

typedef unsigned long long ull;

__device__ double   g_partial[NCTA];
__device__ float    g_ee[NUM_K];
__device__ ull      g_eplow[128 * 65];       // (e_2p[d], e_2p+1[d]) codes 0..255
__device__ uint32_t g_bpack[256 * 36];       // bf16 kword tiles, codes 256..511

__device__ __forceinline__ void fma2(ull &acc, ull a, ull b) {
    asm("fma.rn.f32x2 %0, %1, %2, %0;" : "+l"(acc) : "l"(a), "l"(b));
}
__device__ __forceinline__ float2 unpack2(ull v) {
    float2 r;
    asm("mov.b64 {%0, %1}, %2;" : "=f"(r.x), "=f"(r.y) : "l"(v));
    return r;
}
__device__ __forceinline__ ull dup2(float x) {
    ull r;
    asm("mov.b64 %0, {%1, %1};" : "=l"(r) : "f"(x));
    return r;
}
__device__ __forceinline__ uint32_t bfpack(float a, float b) {
    __nv_bfloat162 h;
    h.x = __float2bfloat16(a);
    h.y = __float2bfloat16(b);
    return *(uint32_t*)&h;
}
__device__ __forceinline__ void mma16816(float& d0, float& d1, float& d2, float& d3,
                                         uint32_t a0, uint32_t a1, uint32_t a2,
                                         uint32_t a3, uint32_t b0, uint32_t b1) {
    asm volatile(
        "mma.sync.aligned.m16n8k16.row.col.f32.bf16.bf16.f32 "
        "{%0,%1,%2,%3}, {%4,%5,%6,%7}, {%8,%9}, {%0,%1,%2,%3};"
        : "+f"(d0), "+f"(d1), "+f"(d2), "+f"(d3)
        : "r"(a0), "r"(a1), "r"(a2), "r"(a3), "r"(b0), "r"(b1));
}

// ---------------------------------------------------------------------------
// Prep: ee (exact chain), pair-interleaved fp32 low half, bf16 kword high half
// ---------------------------------------------------------------------------
__global__ void __launch_bounds__(512)
vq_prep(const float* __restrict__ emb) {
    extern __shared__ float es[];               // [512][65]
    const int tid = threadIdx.x;

#pragma unroll
    for (int it = 0; it < 16; it++) {
        int i = tid + it * 512;                 // float4 index
        int k = i >> 4, q = i & 15;
        float4 v = __ldg((const float4*)(emb + k * DIM + q * 4));
        float* row = es + k * 65 + q * 4;
        row[0] = v.x; row[1] = v.y; row[2] = v.z; row[3] = v.w;
    }
    __syncthreads();

    const float* er = es + tid * 65;
    float ee = 0.f;
#pragma unroll
    for (int d = 0; d < DIM; d++) ee = fmaf(er[d], er[d], ee);   // exact chain
    g_ee[tid] = ee;

    if (tid < 256) {
        // low half: pair-interleaved fp32 (thread = code k, writes its slot)
        int p = tid >> 1, sl = tid & 1;
        float* dst = (float*)(g_eplow + p * 65);
#pragma unroll 8
        for (int d = 0; d < DIM; d++) dst[d * 2 + sl] = er[d];
    } else {
        // high half: bf16 kword layout (R8 pack, proven)
        int r = tid - 256;
#pragma unroll
        for (int w = 0; w < 36; w++) {
            uint32_t val = 0;
            if (w < 32) {
                int ks = w >> 3, j = w & 7;
                int k0 = 16 * ks + 8 * (j & 1) + 2 * (j >> 1);
                val = bfpack(er[k0], er[k0 + 1]);
            }
            g_bpack[r * 36 + w] = val;
        }
    }
}

// ---------------------------------------------------------------------------
__global__ void __launch_bounds__(NTH, 1)
vq_main(const float* __restrict__ inp, const float* __restrict__ emb,
        float* __restrict__ out) {
    extern __shared__ char smem[];
    float*     X    = (float*)(smem + SM_X);
    ull*       EP   = (ull*)(smem + SM_EP);
    uint32_t*  B32  = (uint32_t*)(smem + SM_B);
    float*     see  = (float*)(smem + SM_SEE);
    uint16_t*  BM   = (uint16_t*)(smem + SM_BM);
    float*     redv = (float*)(smem + SM_REDV);
    int*       redi = (int*)(smem + SM_REDI);
    int*       sidx = (int*)(smem + SM_SIDX);
    float*     redw = (float*)(smem + SM_REDW);
    float*     CSTG = (float*)(smem + SM_CSTG);

    const int tid  = threadIdx.x;
    const int wid  = tid >> 5;
    const int lane = tid & 31;

    const int b  = blockIdx.x >> 5;             // 32 tiles of 256 per batch
    const int t0 = (blockIdx.x & 31) * MT;
    const float* xbase = inp + (size_t)b * DIM * T_LEN + t0;

    // ---- fills: X, EP, B, see ----
#pragma unroll
    for (int it = 0; it < 16; it++) {
        int i = tid + it * NTH;
        int d = i >> 6, c = i & 63;
        float4 v = *(const float4*)(xbase + (size_t)d * T_LEN + c * 4);
        *(float4*)(X + d * MT + c * 4) = v;
    }
    for (int i = tid; i < 4160; i += NTH)       // 66560 B
        ((uint4*)EP)[i] = ((const uint4*)g_eplow)[i];
#pragma unroll
    for (int it = 0; it < 9; it++)              // 36864 B
        ((uint4*)B32)[tid + it * NTH] = ((const uint4*)g_bpack)[tid + it * NTH];
#pragma unroll
    for (int it = 0; it < 2; it++) see[tid + it * NTH] = g_ee[tid + it * NTH];
    __syncthreads();

    // ================= phase functions (inlined lambdas) =================
    // EXACT half: codes 0..255 via f32x2 (lane = 2 codes), R2-proven chain.
    auto exact_phase = [&]() {
        const int q  = wid & 3;                 // code quarter (warp-uniform)
        const int h  = wid >> 2;
        const int t2 = lane + 32 * h;           // vector base
        float xx[4];
#pragma unroll
        for (int j = 0; j < 4; j++) {
            float s = 0.f;
#pragma unroll
            for (int d = 0; d < DIM; d++) {
                float v = X[d * MT + t2 + 64 * j];
                s = fmaf(v, v, s);
            }
            xx[j] = s;
        }
        float minv[4] = {3.4e38f, 3.4e38f, 3.4e38f, 3.4e38f};
        int   mini[4] = {0, 0, 0, 0};
        for (int pass = 0; pass < 4; pass++) {
            const int pbase = q * 32 + pass * 8;
            const ull* eprow = EP + pbase * 65;
            ull acc[4][8];
#pragma unroll
            for (int j = 0; j < 4; j++)
#pragma unroll
                for (int p = 0; p < 8; p++) acc[j][p] = 0ull;
#pragma unroll 8
            for (int d = 0; d < DIM; d++) {
                ull xv[4], ev[8];
#pragma unroll
                for (int j = 0; j < 4; j++) xv[j] = dup2(X[d * MT + t2 + 64 * j]);
#pragma unroll
                for (int p = 0; p < 8; p++) ev[p] = eprow[p * 65 + d];
#pragma unroll
                for (int j = 0; j < 4; j++)
#pragma unroll
                    for (int p = 0; p < 8; p++) fma2(acc[j][p], xv[j], ev[p]);
            }
#pragma unroll
            for (int p = 0; p < 8; p++) {
                int k0 = 2 * (pbase + p);
                float e0 = see[k0], e1 = see[k0 + 1];
#pragma unroll
                for (int j = 0; j < 4; j++) {
                    float2 dt = unpack2(acc[j][p]);
                    float d0 = fmaf(-2.f, dt.x, xx[j]) + e0;
                    float d1 = fmaf(-2.f, dt.y, xx[j]) + e1;
                    if (d0 < minv[j]) { minv[j] = d0; mini[j] = k0; }
                    if (d1 < minv[j]) { minv[j] = d1; mini[j] = k0 + 1; }
                }
            }
        }
#pragma unroll
        for (int j = 0; j < 4; j++) {
            redv[q * MT + t2 + 64 * j] = minv[j];
            redi[q * MT + t2 + 64 * j] = mini[j];
        }
    };

    // FILTER half: codes 256..511 via bf16 MMA (R8 mapping), block-min -> BM.
    auto mma_phase = [&]() {
        const int wrow = wid * 32;
        const int qr = lane >> 2, qc = lane & 3;
        uint32_t af[2][4][4];
#pragma unroll
        for (int m2 = 0; m2 < 2; m2++) {
            int r0 = wrow + 16 * m2 + qr;
#pragma unroll
            for (int ks = 0; ks < 4; ks++) {
                int k0 = 16 * ks + 2 * qc;
                af[m2][ks][0] = bfpack(X[(k0    ) * MT + r0],     X[(k0 + 1) * MT + r0]);
                af[m2][ks][1] = bfpack(X[(k0    ) * MT + r0 + 8], X[(k0 + 1) * MT + r0 + 8]);
                af[m2][ks][2] = bfpack(X[(k0 + 8) * MT + r0],     X[(k0 + 9) * MT + r0]);
                af[m2][ks][3] = bfpack(X[(k0 + 8) * MT + r0 + 8], X[(k0 + 9) * MT + r0 + 8]);
            }
        }
#pragma unroll 2
        for (int nt = 0; nt < 32; nt++) {
            const int n0 = nt * 8;
            uint32_t bb0[4], bb1[4];
#pragma unroll
            for (int ks = 0; ks < 4; ks++) {
                uint2 bb = *(uint2*)(B32 + (n0 + qr) * 36 + ks * 8 + 2 * qc);
                bb0[ks] = bb.x; bb1[ks] = bb.y;
            }
            const int cc = 256 + n0 + 2 * qc;
            float e0 = see[cc], e1 = see[cc + 1];
#pragma unroll
            for (int m2 = 0; m2 < 2; m2++) {
                float d0 = 0.f, d1 = 0.f, d2 = 0.f, d3 = 0.f;
#pragma unroll
                for (int ks = 0; ks < 4; ks++)
                    mma16816(d0, d1, d2, d3,
                             af[m2][ks][0], af[m2][ks][1], af[m2][ks][2], af[m2][ks][3],
                             bb0[ks], bb1[ks]);
                float t0 = fminf(fmaf(-2.f, d0, e0), fmaf(-2.f, d1, e1));
                float t1 = fminf(fmaf(-2.f, d2, e0), fmaf(-2.f, d3, e1));
                t0 = fminf(t0, __shfl_xor_sync(0xffffffffu, t0, 1));
                t0 = fminf(t0, __shfl_xor_sync(0xffffffffu, t0, 2));
                t1 = fminf(t1, __shfl_xor_sync(0xffffffffu, t1, 1));
                t1 = fminf(t1, __shfl_xor_sync(0xffffffffu, t1, 2));
                if (qc == 0) {
                    int rr0 = wrow + 16 * m2 + qr;
                    __nv_bfloat16 h0 = __float2bfloat16_rd(t0);
                    __nv_bfloat16 h1 = __float2bfloat16_rd(t1);
                    BM[rr0 * 33 + nt]       = *(uint16_t*)&h0;
                    BM[(rr0 + 8) * 33 + nt] = *(uint16_t*)&h1;
                }
            }
        }
    };

    // ---- staggered execution: one warp per pipe per SMSP at all times ----
    if (wid < 4) { exact_phase(); mma_phase(); }
    else         { mma_phase(); exact_phase(); }
    __syncthreads();

    // ---- per-vector: refine filter half exactly + combine with exact half ----
    {
        const int m = tid;
        float xx = 0.f;
#pragma unroll
        for (int d = 0; d < DIM; d++) {
            float v = X[d * MT + m];
            xx = fmaf(v, v, xx);
        }
        // threshold over BM row
        float mn = 3.4e38f;
#pragma unroll 8
        for (int nt = 0; nt < 32; nt++) {
            uint32_t u = (uint32_t)BM[m * 33 + nt] << 16;
            mn = fminf(mn, __uint_as_float(u));
        }
        const float th = mn + CAND_W;
        float bv1 = 3.4e38f;
        int   bk1 = 0x7fffffff;
        for (int nt = 0; nt < 32; nt++) {
            uint32_t u = (uint32_t)BM[m * 33 + nt] << 16;
            if (__uint_as_float(u) <= th) {
#pragma unroll 2
                for (int kk = 0; kk < 8; kk++) {
                    int k = 256 + nt * 8 + kk;
                    float ev[DIM];
#pragma unroll
                    for (int qq = 0; qq < 16; qq++) {
                        float4 v = __ldg((const float4*)(emb + k * DIM) + qq);
                        ev[4 * qq + 0] = v.x; ev[4 * qq + 1] = v.y;
                        ev[4 * qq + 2] = v.z; ev[4 * qq + 3] = v.w;
                    }
                    float s = 0.f;
#pragma unroll
                    for (int d = 0; d < DIM; d++) s = fmaf(X[d * MT + m], ev[d], s);
                    float dist = fmaf(-2.f, s, xx) + see[k];
                    if (dist < bv1) { bv1 = dist; bk1 = k; }
                }
            }
        }
        // exact half reduction (q ascending == code ascending, strict <)
        float bv0 = redv[m];
        int   bk0 = redi[m];
#pragma unroll
        for (int q = 1; q < 4; q++) {
            float v = redv[q * MT + m];
            if (v < bv0) { bv0 = v; bk0 = redi[q * MT + m]; }
        }
        int bi = (bv1 < bv0) ? bk1 : bk0;       // ties -> low half (lower k)
        sidx[m] = bi;
        out[IDX_OFF + (size_t)b * T_LEN + t0 + m] = (float)bi;
    }
    __syncthreads();

    // ---- quantized write + loss, 2 staged chunks over dead B arena ----
    float* qbase = out + (size_t)b * DIM * T_LEN + t0;
    float lacc = 0.f;
#pragma unroll
    for (int chunk = 0; chunk < 2; chunk++) {
        __syncthreads();
        for (int r = wid; r < 128; r += 8) {
            int k = sidx[chunk * 128 + r];
            float2 v = __ldg((const float2*)(emb + k * DIM) + lane);
            CSTG[r * 65 + 2 * lane + 0] = v.x;
            CSTG[r * 65 + 2 * lane + 1] = v.y;
        }
        __syncthreads();
#pragma unroll
        for (int it = 0; it < 8; it++) {
            int i = tid + it * NTH;
            int d = i >> 5, cc = i & 31;
            int r0 = cc * 4;
            int m0 = chunk * 128 + r0;
            float4 qv;
            qv.x = CSTG[(r0 + 0) * 65 + d];
            qv.y = CSTG[(r0 + 1) * 65 + d];
            qv.z = CSTG[(r0 + 2) * 65 + d];
            qv.w = CSTG[(r0 + 3) * 65 + d];
            *(float4*)(qbase + (size_t)d * T_LEN + m0) = qv;
            const float* xr = X + d * MT + m0;
            float dx;
            dx = qv.x - xr[0]; lacc = fmaf(dx, dx, lacc);
            dx = qv.y - xr[1]; lacc = fmaf(dx, dx, lacc);
            dx = qv.z - xr[2]; lacc = fmaf(dx, dx, lacc);
            dx = qv.w - xr[3]; lacc = fmaf(dx, dx, lacc);
        }
    }
#pragma unroll
    for (int off = 16; off; off >>= 1)
        lacc += __shfl_xor_sync(0xffffffffu, lacc, off);
    if (lane == 0) redw[wid] = lacc;
    __syncthreads();
    if (tid == 0) {
        double s = 0.0;
#pragma unroll
        for (int w = 0; w < 8; w++) s += (double)redw[w];
        g_partial[blockIdx.x] = s;
    }
}

// ---------------------------------------------------------------------------
__global__ void __launch_bounds__(32)
vq_loss(float* __restrict__ out) {
    int lane = threadIdx.x;
    double s = 0.0;
    for (int i = 0; i < NCTA / 32; i++)
        s += g_partial[lane * (NCTA / 32) + i];
#pragma unroll
    for (int off = 16; off; off >>= 1)
        s += __shfl_xor_sync(0xffffffffu, s, off);
    if (lane == 0)
        out[LOSS_OFF] = (float)(s * (1.25 / (double)((size_t)B_LEN * DIM * T_LEN)));
}

// ---------------------------------------------------------------------------
extern "C" void kernel_launch(void* const* d_in, const int* in_sizes, int n_in,
                              void* d_out, int out_size) {
    const float* inp = (const float*)d_in[0];   // [32, 64, 8192] f32
    const float* emb = (const float*)d_in[1];   // [512, 64] f32
    float* out = (float*)d_out;

    cudaFuncSetAttribute(vq_prep, cudaFuncAttributeMaxDynamicSharedMemorySize,
                         512 * 65 * 4);
    cudaFuncSetAttribute(vq_main, cudaFuncAttributeMaxDynamicSharedMemorySize,
                         SMEM_BYTES);
    vq_prep<<<1, NUM_K, 512 * 65 * 4>>>(emb);
    vq_main<<<NCTA, NTH, SMEM_BYTES>>>(inp, emb, out);
    vq_loss<<<1, 32>>>(out);
}